// round 10
// baseline (speedup 1.0000x reference)
#include <cuda_runtime.h>
#include <math.h>
#include <stdint.h>

// Problem constants: B=64, S=2048, I=256, H=256, G=2H=512
#define BATCH 64
#define SEQ   2048
#define HID   256
#define GATES 512
#define WROWS 272          // rows in global transposed weights (>=256 zero)
#define ZROW  256          // all-zero row index (global sentinel)
#define TCACHE 96          // weight rows cached in smem (Wi1, Wh0)
#define SZROW  96          // smem sentinel zero row index

// -------- scratch (static device arrays; no allocation) --------
__device__ float g_gx[67108864];          // (B*S, 512) fp32 = 256 MB
__device__ float g_WhT0[WROWS * GATES];   // [j][g]
__device__ float g_WiT1[WROWS * GATES];
__device__ float g_WhT1[WROWS * GATES];

// ---------------------------------------------------------------
// Kernel 0: transpose weights into padded [j][g] layout; zero pad rows.
// ---------------------------------------------------------------
__global__ void prep_kernel(const float* __restrict__ Wh0,
                            const float* __restrict__ Wi1,
                            const float* __restrict__ Wh1)
{
    int idx = blockIdx.x * 256 + threadIdx.x;
    const int perp = WROWS * GATES;
    if (idx < 3 * perp) {
        int m = idx / perp;
        int e = idx - m * perp;
        int j = e >> 9;
        int g = e & 511;
        const float* src = (m == 0) ? Wh0 : (m == 1) ? Wi1 : Wh1;
        float*       dst = (m == 0) ? g_WhT0 : (m == 1) ? g_WiT1 : g_WhT1;
        dst[e] = (j < HID) ? src[g * HID + j] : 0.0f;
    }
}

// ---------------------------------------------------------------
// Kernel 1: gx0 = (x @ Wi0^T + bi0) + bh0   (unchanged — passing)
// ---------------------------------------------------------------
__global__ void __launch_bounds__(256, 2)
gemm_gx_kernel(const float* __restrict__ x,
               const float* __restrict__ Wi0,
               const float* __restrict__ bi0,
               const float* __restrict__ bh0)
{
    __shared__ float As[32][68];
    __shared__ float Bs[32][68];

    const int m0  = blockIdx.x * 64;
    const int n0  = blockIdx.y * 64;
    const int tid = threadIdx.x;
    const int tx  = tid & 15;
    const int ty  = tid >> 4;

    float acc[4][4];
#pragma unroll
    for (int i = 0; i < 4; i++)
#pragma unroll
        for (int j = 0; j < 4; j++) acc[i][j] = 0.f;

    for (int k0 = 0; k0 < 256; k0 += 32) {
#pragma unroll
        for (int v = 0; v < 2; v++) {
            int idx = tid + v * 256;
            int r   = idx >> 3;
            int kk  = (idx & 7) << 2;
            float4 av = *reinterpret_cast<const float4*>(
                x + (size_t)(m0 + r) * 256 + (k0 + kk));
            As[kk + 0][r] = av.x; As[kk + 1][r] = av.y;
            As[kk + 2][r] = av.z; As[kk + 3][r] = av.w;
            float4 bv = *reinterpret_cast<const float4*>(
                Wi0 + (size_t)(n0 + r) * 256 + (k0 + kk));
            Bs[kk + 0][r] = bv.x; Bs[kk + 1][r] = bv.y;
            Bs[kk + 2][r] = bv.z; Bs[kk + 3][r] = bv.w;
        }
        __syncthreads();
#pragma unroll
        for (int k = 0; k < 32; k++) {
            float4 av = *reinterpret_cast<const float4*>(&As[k][ty << 2]);
            float4 bv = *reinterpret_cast<const float4*>(&Bs[k][tx << 2]);
            float aa[4] = {av.x, av.y, av.z, av.w};
            float bb[4] = {bv.x, bv.y, bv.z, bv.w};
#pragma unroll
            for (int i = 0; i < 4; i++)
#pragma unroll
                for (int j = 0; j < 4; j++)
                    acc[i][j] = __fmaf_rn(aa[i], bb[j], acc[i][j]);
        }
        __syncthreads();
    }

    float4 b1 = *reinterpret_cast<const float4*>(bi0 + n0 + (tx << 2));
    float4 b2 = *reinterpret_cast<const float4*>(bh0 + n0 + (tx << 2));

#pragma unroll
    for (int i = 0; i < 4; i++) {
        int r = m0 + (ty << 2) + i;
        float4 o;
        o.x = __fadd_rn(__fadd_rn(acc[i][0], b1.x), b2.x);
        o.y = __fadd_rn(__fadd_rn(acc[i][1], b1.y), b2.y);
        o.z = __fadd_rn(__fadd_rn(acc[i][2], b1.z), b2.z);
        o.w = __fadd_rn(__fadd_rn(acc[i][3], b1.w), b2.w);
        *reinterpret_cast<float4*>(g_gx + (size_t)r * GATES + n0 + (tx << 2)) = o;
    }
}

// ---------------------------------------------------------------
// Cluster helpers (2-CTA clusters)
// ---------------------------------------------------------------
__device__ __forceinline__ unsigned ctarank()
{
    unsigned r;
    asm("mov.u32 %0, %%cluster_ctarank;" : "=r"(r));
    return r;
}

#define CLUSTER_SYNC() do {                                            \
    asm volatile("barrier.cluster.arrive.aligned;" ::: "memory");      \
    asm volatile("barrier.cluster.wait.aligned;"   ::: "memory");      \
} while (0)

__device__ __forceinline__ void remote_st_u32(void* lptr, int rank, unsigned val)
{
    unsigned laddr;
    asm("{ .reg .u64 t; cvta.to.shared.u64 t, %1; cvt.u32.u64 %0, t; }"
        : "=r"(laddr) : "l"(lptr));
    unsigned raddr;
    asm volatile("mapa.shared::cluster.u32 %0, %1, %2;"
                 : "=r"(raddr) : "r"(laddr), "r"(rank));
    asm volatile("st.shared::cluster.u32 [%0], %1;"
                 :: "r"(raddr), "r"(val) : "memory");
}

// XLA logistic: 1/(1+exp(-x)), exp via fp64 rounded to f32 (passing numerics).
__device__ __forceinline__ float sigmoid_ref(float g)
{
    float ef = (float)exp(-(double)g);
    return __fdiv_rn(1.0f, __fadd_rn(1.0f, ef));
}

// ---------------------------------------------------------------
// float2 matvecs. Strictly ascending-j single-accumulator chains per
// component; out-of-range slots select the all-zero sentinel row
// (+0.0f adds, exact no-ops). No predication on addresses.
// ---------------------------------------------------------------
__device__ __forceinline__ float2 mv2_smem(const float* __restrict__ Ws,
                                           const int* __restrict__ lst, int s)
{
    float2 m = make_float2(0.f, 0.f);
    for (int i = 0; i < s; i += 8) {
        float2 w[8];
#pragma unroll
        for (int u = 0; u < 8; u++) {
            int idx = i + u;
            int j = (idx < s) ? lst[idx] : SZROW;
            w[u] = *reinterpret_cast<const float2*>(Ws + (j << 8));
        }
#pragma unroll
        for (int u = 0; u < 8; u++) {
            m.x = __fadd_rn(m.x, w[u].x);
            m.y = __fadd_rn(m.y, w[u].y);
        }
    }
    return m;
}

__device__ __forceinline__ float2 mv2_global(float2 m,
                                             const float* __restrict__ Wg,
                                             const int* __restrict__ lst,
                                             int from, int n)
{
    for (int i = from; i < n; i += 16) {
        float2 w[16];
#pragma unroll
        for (int u = 0; u < 16; u++) {
            int idx = i + u;
            int j = (idx < n) ? lst[idx] : ZROW;
            w[u] = *reinterpret_cast<const float2*>(Wg + ((size_t)j << 9));
        }
#pragma unroll
        for (int u = 0; u < 16; u++) {
            m.x = __fadd_rn(m.x, w[u].x);
            m.y = __fadd_rn(m.y, w[u].y);
        }
    }
    return m;
}

// local pair index k in [0,128) -> global gate col of pair base (2k,2k+1)
__device__ __forceinline__ int paircol(int k, int rank)
{
    int c = 2 * k;
    return (c < 128) ? (rank * 128 + c) : (256 + rank * 128 + (c - 128));
}

// ---------------------------------------------------------------
// Kernel 2: spiking-LSTM scan. 64 clusters x 2 CTAs (128 CTAs).
// CTA rank r owns hidden units [128r,128r+128). Wi1/Wh0 rows 0..95 live
// in smem; tails stream from L2. Wh0.h0(t) precomputed in phase 2 of t.
//   phase 1: warps 8-11: Wh1.h1(t-1) (float2) | warps 0-3: L0 update
//            warps 4-7: gx prefetch for t+1
//   phase 2: warps 0-3: Wi1.h0(t) | warps 4-7: Wh0.h0(t)  (smem prefix
//            + global tail, same accumulator chain)
// ---------------------------------------------------------------
__global__ void __launch_bounds__(512, 1) __cluster_dims__(2, 1, 1)
recurrent2(const float* __restrict__ bi1,
           const float* __restrict__ bh1,
           float* __restrict__ out)
{
    extern __shared__ float dyn[];
    float* Wi1sm = dyn;                         // [97][256]
    float* Wh0sm = dyn + 97 * 256;              // [97][256]

    const int tid  = threadIdx.x;
    const int lane = tid & 31;
    const int warp = tid >> 5;
    const int rank = (int)ctarank();
    const int b    = blockIdx.x >> 1;

    __shared__ float gxs[512];                  // double-buffered gx [2][256]
    __shared__ float m0s[256];                  // Wh0 . h0 (precomputed)
    __shared__ float mhs[256];                  // Wh1 . h1(t-1)
    __shared__ float g1s[256];                  // layer-1 gates
    __shared__ float c0s[128], c1s[128];
    __shared__ int   lst0[288], lst1[288];
    __shared__ unsigned msk0[8], msk1[8];
    __shared__ int n0s, n1s, s0s;

    // ---- load smem weight caches (rows 0..95 + zero row 96) ----
    for (int idx = tid; idx < 97 * 256; idx += 512) {
        int j = idx >> 8;
        int c = idx & 255;
        int gg = (c < 128) ? (rank * 128 + c) : (256 + rank * 128 + (c - 128));
        Wi1sm[idx] = (j < TCACHE) ? g_WiT1[j * GATES + gg] : 0.0f;
        Wh0sm[idx] = (j < TCACHE) ? g_WhT0[j * GATES + gg] : 0.0f;
    }
    if (tid < 256) m0s[tid] = 0.f;
    if (tid < 128) { c0s[tid] = 0.f; c1s[tid] = 0.f; }
    if (tid == 0)  { n0s = 0; n1s = 0; s0s = 0; }

    const int ubase = rank * 128;               // first owned hidden unit
    const float* gxb = g_gx + (size_t)b * ((size_t)SEQ * GATES);

    // per-role constants
    float2 bi1v = make_float2(0.f, 0.f), bh1v = make_float2(0.f, 0.f);
    if (tid < 128) {
        int g0 = paircol(tid, rank);
        bi1v = *reinterpret_cast<const float2*>(bi1 + g0);
        bh1v = *reinterpret_cast<const float2*>(bh1 + g0);
    }

    // prefetch gx for t=0
    if (tid >= 128 && tid < 256) {
        int v = tid - 128;
        gxs[v]       = __ldcg(gxb + (ubase + v));
        gxs[128 + v] = __ldcg(gxb + (256 + ubase + v));
    }
    __syncthreads();

    for (int t = 0; t < SEQ; ++t) {
        const int pbuf = (t & 1) * 256;

        // ---------------- phase 1 ----------------
        if (tid >= 256 && tid < 384) {
            int k  = tid - 256;
            int g0 = paircol(k, rank);
            float2 mh = mv2_global(make_float2(0.f, 0.f),
                                   g_WhT1 + g0, lst1, 0, n1s);
            *reinterpret_cast<float2*>(&mhs[2 * k]) = mh;
        } else if (tid < 128) {
            // L0 update: gates = gx + m0 (precomputed last step)
            float g  = __fadd_rn(gxs[pbuf + tid],       m0s[tid]);
            float ct = __fadd_rn(gxs[pbuf + 128 + tid], m0s[128 + tid]);
            float f  = sigmoid_ref(g);
            float cc = __fadd_rn(__fmul_rn(f, c0s[tid]),
                                 __fmul_rn(__fsub_rn(1.0f, f), ct));
            c0s[tid] = cc;
            unsigned bal = __ballot_sync(0xffffffffu, cc > 0.f);
            if (lane == 0) {
                msk0[4 * rank + warp] = bal;
                remote_st_u32(&msk0[4 * rank + warp], rank ^ 1, bal);
            }
        } else if (tid < 256) {
            // prefetch gx for t+1
            int tn = t + 1;
            if (tn < SEQ) {
                int v = tid - 128;
                int nb = (tn & 1) * 256;
                gxs[nb + v]       = __ldcg(gxb + (size_t)tn * GATES + (ubase + v));
                gxs[nb + 128 + v] = __ldcg(gxb + (size_t)tn * GATES + (256 + ubase + v));
            }
        }
        CLUSTER_SYNC();                          // masks0 + mhs visible

        // ---------------- build lst0 (ascending) ----------------
        if (tid < 256) {
            int j = tid, pre = 0, tot = 0;
            unsigned mw = 0;
#pragma unroll
            for (int w = 0; w < 8; w++) {
                unsigned mm = msk0[w];
                tot += __popc(mm);
                if (w < (j >> 5)) pre += __popc(mm);
                else if (w == (j >> 5)) {
                    mw = mm;
                    pre += __popc(mm & ((1u << (j & 31)) - 1u));
                }
            }
            if ((mw >> (j & 31)) & 1u) lst0[pre] = j;
            if (j == 0) {
                n0s = tot;
                s0s = __popc(msk0[0]) + __popc(msk0[1]) + __popc(msk0[2]);
            }
        }
        __syncthreads();

        // ---------------- phase 2 ----------------
        if (tid < 128) {
            int k  = tid;
            int g0 = paircol(k, rank);
            float2 mi = mv2_smem(Wi1sm + 2 * k, lst0, s0s);
            mi = mv2_global(mi, g_WiT1 + g0, lst0, s0s, n0s);
            float2 gi, g2;
            gi.x = __fadd_rn(__fadd_rn(mi.x, bi1v.x), bh1v.x);
            gi.y = __fadd_rn(__fadd_rn(mi.y, bi1v.y), bh1v.y);
            float2 mh = *reinterpret_cast<const float2*>(&mhs[2 * k]);
            g2.x = __fadd_rn(gi.x, mh.x);
            g2.y = __fadd_rn(gi.y, mh.y);
            *reinterpret_cast<float2*>(&g1s[2 * k]) = g2;
        } else if (tid < 256) {
            int k  = tid - 128;
            int g0 = paircol(k, rank);
            float2 m0 = mv2_smem(Wh0sm + 2 * k, lst0, s0s);
            m0 = mv2_global(m0, g_WhT0 + g0, lst0, s0s, n0s);
            *reinterpret_cast<float2*>(&m0s[2 * k]) = m0;
        }
        __syncthreads();

        // ---------------- L1 update + output ----------------
        if (tid < 128) {
            float f  = sigmoid_ref(g1s[tid]);
            float ct = g1s[128 + tid];
            float cc = __fadd_rn(__fmul_rn(f, c1s[tid]),
                                 __fmul_rn(__fsub_rn(1.0f, f), ct));
            c1s[tid] = cc;
            float h  = (cc > 0.f) ? 1.f : 0.f;
            out[((size_t)b * SEQ + t) * HID + (ubase + tid)] = h;
            unsigned bal = __ballot_sync(0xffffffffu, cc > 0.f);
            if (lane == 0) {
                msk1[4 * rank + warp] = bal;
                remote_st_u32(&msk1[4 * rank + warp], rank ^ 1, bal);
            }
        }
        CLUSTER_SYNC();                          // masks1 visible

        // ---------------- build lst1 ----------------
        if (tid < 256) {
            int j = tid, pre = 0, tot = 0;
            unsigned mw = 0;
#pragma unroll
            for (int w = 0; w < 8; w++) {
                unsigned mm = msk1[w];
                tot += __popc(mm);
                if (w < (j >> 5)) pre += __popc(mm);
                else if (w == (j >> 5)) {
                    mw = mm;
                    pre += __popc(mm & ((1u << (j & 31)) - 1u));
                }
            }
            if ((mw >> (j & 31)) & 1u) lst1[pre] = j;
            if (j == 0) n1s = tot;
        }
        __syncthreads();
    }

    // finals: h_n (2,B,H) then c_n (2,B,H) after the (B,S,H) output
    if (tid < 128) {
        const size_t HN = (size_t)BATCH * SEQ * HID;
        const size_t CN = HN + (size_t)2 * BATCH * HID;
        const int ui = ubase + tid;
        float cc0 = c0s[tid], cc1 = c1s[tid];
        out[HN + ((size_t)0 * BATCH + b) * HID + ui] = (cc0 > 0.f) ? 1.f : 0.f;
        out[HN + ((size_t)1 * BATCH + b) * HID + ui] = (cc1 > 0.f) ? 1.f : 0.f;
        out[CN + ((size_t)0 * BATCH + b) * HID + ui] = cc0;
        out[CN + ((size_t)1 * BATCH + b) * HID + ui] = cc1;
    }
}

// ---------------------------------------------------------------
extern "C" void kernel_launch(void* const* d_in, const int* in_sizes, int n_in,
                              void* d_out, int out_size)
{
    const float* x   = (const float*)d_in[0];
    const float* Wi0 = (const float*)d_in[1];
    const float* bi0 = (const float*)d_in[2];
    const float* Wh0 = (const float*)d_in[3];
    const float* bh0 = (const float*)d_in[4];
    const float* Wi1 = (const float*)d_in[5];
    const float* bi1 = (const float*)d_in[6];
    const float* Wh1 = (const float*)d_in[7];
    const float* bh1 = (const float*)d_in[8];
    float* out = (float*)d_out;

    const int dsmem = 2 * 97 * 256 * (int)sizeof(float);   // 198656 B
    static int configured = 0;
    cudaFuncSetAttribute(recurrent2,
                         cudaFuncAttributeMaxDynamicSharedMemorySize, dsmem);
    (void)configured;

    prep_kernel<<<1632, 256>>>(Wh0, Wi1, Wh1);

    dim3 gg(2048, 8);
    gemm_gx_kernel<<<gg, 256>>>(x, Wi0, bi0, bh0);

    recurrent2<<<BATCH * 2, 512, dsmem>>>(bi1, bh1, out);
}

// round 11
// speedup vs baseline: 1.2345x; 1.2345x over previous
#include <cuda_runtime.h>
#include <math.h>
#include <stdint.h>

// Problem constants: B=64, S=2048, I=256, H=256, G=2H=512
#define BATCH 64
#define SEQ   2048
#define HID   256
#define GATES 512
#define WROWS 272          // rows in global transposed weights (>=256 zero)
#define ZROW  256          // all-zero row index (sentinel)

// -------- scratch (static device arrays; no allocation) --------
__device__ float g_gx[67108864];          // (B*S, 512) fp32 = 256 MB
__device__ float g_WhT0[WROWS * GATES];   // [j][g]
__device__ float g_WiT1[WROWS * GATES];
__device__ float g_WhT1[WROWS * GATES];

// ---------------------------------------------------------------
// Kernel 0: transpose weights into padded [j][g] layout; zero pad rows.
// ---------------------------------------------------------------
__global__ void prep_kernel(const float* __restrict__ Wh0,
                            const float* __restrict__ Wi1,
                            const float* __restrict__ Wh1)
{
    int idx = blockIdx.x * 256 + threadIdx.x;
    const int perp = WROWS * GATES;
    if (idx < 3 * perp) {
        int m = idx / perp;
        int e = idx - m * perp;
        int j = e >> 9;
        int g = e & 511;
        const float* src = (m == 0) ? Wh0 : (m == 1) ? Wi1 : Wh1;
        float*       dst = (m == 0) ? g_WhT0 : (m == 1) ? g_WiT1 : g_WhT1;
        dst[e] = (j < HID) ? src[g * HID + j] : 0.0f;
    }
}

// ---------------------------------------------------------------
// Kernel 1: gx0 = (x @ Wi0^T + bi0) + bh0   (unchanged — passing)
// ---------------------------------------------------------------
__global__ void __launch_bounds__(256, 2)
gemm_gx_kernel(const float* __restrict__ x,
               const float* __restrict__ Wi0,
               const float* __restrict__ bi0,
               const float* __restrict__ bh0)
{
    __shared__ float As[32][68];
    __shared__ float Bs[32][68];

    const int m0  = blockIdx.x * 64;
    const int n0  = blockIdx.y * 64;
    const int tid = threadIdx.x;
    const int tx  = tid & 15;
    const int ty  = tid >> 4;

    float acc[4][4];
#pragma unroll
    for (int i = 0; i < 4; i++)
#pragma unroll
        for (int j = 0; j < 4; j++) acc[i][j] = 0.f;

    for (int k0 = 0; k0 < 256; k0 += 32) {
#pragma unroll
        for (int v = 0; v < 2; v++) {
            int idx = tid + v * 256;
            int r   = idx >> 3;
            int kk  = (idx & 7) << 2;
            float4 av = *reinterpret_cast<const float4*>(
                x + (size_t)(m0 + r) * 256 + (k0 + kk));
            As[kk + 0][r] = av.x; As[kk + 1][r] = av.y;
            As[kk + 2][r] = av.z; As[kk + 3][r] = av.w;
            float4 bv = *reinterpret_cast<const float4*>(
                Wi0 + (size_t)(n0 + r) * 256 + (k0 + kk));
            Bs[kk + 0][r] = bv.x; Bs[kk + 1][r] = bv.y;
            Bs[kk + 2][r] = bv.z; Bs[kk + 3][r] = bv.w;
        }
        __syncthreads();
#pragma unroll
        for (int k = 0; k < 32; k++) {
            float4 av = *reinterpret_cast<const float4*>(&As[k][ty << 2]);
            float4 bv = *reinterpret_cast<const float4*>(&Bs[k][tx << 2]);
            float aa[4] = {av.x, av.y, av.z, av.w};
            float bb[4] = {bv.x, bv.y, bv.z, bv.w};
#pragma unroll
            for (int i = 0; i < 4; i++)
#pragma unroll
                for (int j = 0; j < 4; j++)
                    acc[i][j] = __fmaf_rn(aa[i], bb[j], acc[i][j]);
        }
        __syncthreads();
    }

    float4 b1 = *reinterpret_cast<const float4*>(bi0 + n0 + (tx << 2));
    float4 b2 = *reinterpret_cast<const float4*>(bh0 + n0 + (tx << 2));

#pragma unroll
    for (int i = 0; i < 4; i++) {
        int r = m0 + (ty << 2) + i;
        float4 o;
        o.x = __fadd_rn(__fadd_rn(acc[i][0], b1.x), b2.x);
        o.y = __fadd_rn(__fadd_rn(acc[i][1], b1.y), b2.y);
        o.z = __fadd_rn(__fadd_rn(acc[i][2], b1.z), b2.z);
        o.w = __fadd_rn(__fadd_rn(acc[i][3], b1.w), b2.w);
        *reinterpret_cast<float4*>(g_gx + (size_t)r * GATES + n0 + (tx << 2)) = o;
    }
}

// ---------------------------------------------------------------
// Cluster helpers (2-CTA clusters)
// ---------------------------------------------------------------
__device__ __forceinline__ unsigned ctarank()
{
    unsigned r;
    asm("mov.u32 %0, %%cluster_ctarank;" : "=r"(r));
    return r;
}

#define CLUSTER_SYNC() do {                                            \
    asm volatile("barrier.cluster.arrive.aligned;" ::: "memory");      \
    asm volatile("barrier.cluster.wait.aligned;"   ::: "memory");      \
} while (0)

__device__ __forceinline__ void remote_st_u32(void* lptr, int rank, unsigned val)
{
    unsigned laddr;
    asm("{ .reg .u64 t; cvta.to.shared.u64 t, %1; cvt.u32.u64 %0, t; }"
        : "=r"(laddr) : "l"(lptr));
    unsigned raddr;
    asm volatile("mapa.shared::cluster.u32 %0, %1, %2;"
                 : "=r"(raddr) : "r"(laddr), "r"(rank));
    asm volatile("st.shared::cluster.u32 [%0], %1;"
                 :: "r"(raddr), "r"(val) : "memory");
}

// XLA logistic: 1/(1+exp(-x)), exp via fp64 rounded to f32 (passing numerics).
__device__ __forceinline__ float sigmoid_ref(float g)
{
    float ef = (float)exp(-(double)g);
    return __fdiv_rn(1.0f, __fadd_rn(1.0f, ef));
}

// ---------------------------------------------------------------
// Scalar active-row sum for one gate column, explicitly double-buffered:
// batch k+1's 16 independent LDGs are issued BEFORE batch k's adds, so
// L2 latency overlaps the FADD chain. Single ascending-j fadd chain;
// list is padded with >=16 extra ZROW entries beyond n16, so the
// one-past-the-end batch load is safe (all-zero row, L1-resident).
// ---------------------------------------------------------------
__device__ __forceinline__ float matvec_col(const float* __restrict__ Wg,
                                            const int* __restrict__ lst,
                                            int n16)
{
    float acc = 0.f;
    const int4* l4 = reinterpret_cast<const int4*>(lst);
    const int nb = n16 >> 4;
    if (nb == 0) return acc;

    float w[16];
    {
        int4 a = l4[0], b = l4[1], c = l4[2], d = l4[3];
        w[0]  = __ldg(Wg + (a.x << 9));
        w[1]  = __ldg(Wg + (a.y << 9));
        w[2]  = __ldg(Wg + (a.z << 9));
        w[3]  = __ldg(Wg + (a.w << 9));
        w[4]  = __ldg(Wg + (b.x << 9));
        w[5]  = __ldg(Wg + (b.y << 9));
        w[6]  = __ldg(Wg + (b.z << 9));
        w[7]  = __ldg(Wg + (b.w << 9));
        w[8]  = __ldg(Wg + (c.x << 9));
        w[9]  = __ldg(Wg + (c.y << 9));
        w[10] = __ldg(Wg + (c.z << 9));
        w[11] = __ldg(Wg + (c.w << 9));
        w[12] = __ldg(Wg + (d.x << 9));
        w[13] = __ldg(Wg + (d.y << 9));
        w[14] = __ldg(Wg + (d.z << 9));
        w[15] = __ldg(Wg + (d.w << 9));
    }
    for (int k = 1; k <= nb; k++) {
        // issue next batch's loads first (batch nb reads ZROW pads — safe)
        int4 a = l4[k * 4 + 0], b = l4[k * 4 + 1];
        int4 c = l4[k * 4 + 2], d = l4[k * 4 + 3];
        float wn[16];
        wn[0]  = __ldg(Wg + (a.x << 9));
        wn[1]  = __ldg(Wg + (a.y << 9));
        wn[2]  = __ldg(Wg + (a.z << 9));
        wn[3]  = __ldg(Wg + (a.w << 9));
        wn[4]  = __ldg(Wg + (b.x << 9));
        wn[5]  = __ldg(Wg + (b.y << 9));
        wn[6]  = __ldg(Wg + (b.z << 9));
        wn[7]  = __ldg(Wg + (b.w << 9));
        wn[8]  = __ldg(Wg + (c.x << 9));
        wn[9]  = __ldg(Wg + (c.y << 9));
        wn[10] = __ldg(Wg + (c.z << 9));
        wn[11] = __ldg(Wg + (c.w << 9));
        wn[12] = __ldg(Wg + (d.x << 9));
        wn[13] = __ldg(Wg + (d.y << 9));
        wn[14] = __ldg(Wg + (d.z << 9));
        wn[15] = __ldg(Wg + (d.w << 9));
        // accumulate current batch (strictly ascending order)
#pragma unroll
        for (int u = 0; u < 16; u++) acc = __fadd_rn(acc, w[u]);
#pragma unroll
        for (int u = 0; u < 16; u++) w[u] = wn[u];
    }
    return acc;
}

// ---------------------------------------------------------------
// Kernel 2: spiking-LSTM scan. 64 clusters x 2 CTAs (128 CTAs).
// CTA rank r owns hidden units [128r,128r+128). Weights stream from
// L2/L1 (no smem carveout — L1 capacity is load-bearing here).
// Pipelined: Wh0.h0(t) computed in phase 2 of step t for step t+1.
//   phase 1: tid 256-511: Wh1.h1(t-1) | tid 0-127: L0 update
//            tid 128-255: gx prefetch for t+1
//   phase 2: tid 0-255: Wi1.h0(t) | tid 256-511: Wh0.h0(t)
// ---------------------------------------------------------------
__global__ void __launch_bounds__(512, 1) __cluster_dims__(2, 1, 1)
recurrent2(const float* __restrict__ bi1,
           const float* __restrict__ bh1,
           float* __restrict__ out)
{
    const int tid  = threadIdx.x;
    const int lane = tid & 31;
    const int warp = tid >> 5;
    const int rank = (int)ctarank();
    const int b    = blockIdx.x >> 1;

    __shared__ float gxs[512];     // double-buffered gx [2][256]
    __shared__ float m0s[256];     // Wh0 . h0 (precomputed, local cols)
    __shared__ float mhs[256];     // Wh1 . h1(t-1)
    __shared__ float g1s[256];     // layer-1 gates (local cols)
    __shared__ float c0s[128], c1s[128];
    __shared__ alignas(16) int lst0[288], lst1[288];
    __shared__ unsigned msk0[8], msk1[8];
    __shared__ int n0s, n1s;

    // local column k -> global gate index
    const int k256 = tid & 255;
    const int ggc  = (k256 < 128) ? (rank * 128 + k256)
                                  : (256 + rank * 128 + (k256 - 128));

    if (tid < 256) m0s[tid] = 0.f;
    if (tid < 128) { c0s[tid] = 0.f; c1s[tid] = 0.f; }
    if (tid == 0)  { n0s = 0; n1s = 0; }
    // pad both lists fully so step-0 matvecs (n=0) and first pads are safe
    if (tid < 288) { lst0[tid] = ZROW; lst1[tid] = ZROW; }

    float bi1v = 0.f, bh1v = 0.f;
    if (tid < 256) { bi1v = bi1[ggc]; bh1v = bh1[ggc]; }

    const float* gxb = g_gx + (size_t)b * ((size_t)SEQ * GATES);
    const int ubase  = rank * 128;            // first owned hidden unit

    // prefetch gx for t=0 into buffer 0
    if (tid >= 128 && tid < 256) {
        int v = tid - 128;
        gxs[v]       = __ldcg(gxb + (ubase + v));
        gxs[128 + v] = __ldcg(gxb + (256 + ubase + v));
    }
    __syncthreads();

    for (int t = 0; t < SEQ; ++t) {
        const int pbuf = (t & 1) * 256;

        // ---------------- phase 1 ----------------
        if (tid >= 256) {
            // mh = Wh1 . h1(t-1) for local column k256
            mhs[k256] = matvec_col(g_WhT1 + ggc, lst1, n1s);
        } else if (tid < 128) {
            // L0 update: gates = gx(prefetched) + m0 (precomputed)
            float g  = __fadd_rn(gxs[pbuf + tid],       m0s[tid]);
            float ct = __fadd_rn(gxs[pbuf + 128 + tid], m0s[128 + tid]);
            float f  = sigmoid_ref(g);
            float cc = __fadd_rn(__fmul_rn(f, c0s[tid]),
                                 __fmul_rn(__fsub_rn(1.0f, f), ct));
            c0s[tid] = cc;
            unsigned bal = __ballot_sync(0xffffffffu, cc > 0.f);
            if (lane == 0) {
                msk0[4 * rank + warp] = bal;
                remote_st_u32(&msk0[4 * rank + warp], rank ^ 1, bal);
            }
        } else {
            // prefetch gx for t+1 into the other buffer
            int tn = t + 1;
            if (tn < SEQ) {
                int v  = tid - 128;
                int nb = (tn & 1) * 256;
                gxs[nb + v]       = __ldcg(gxb + (size_t)tn * GATES + (ubase + v));
                gxs[nb + 128 + v] = __ldcg(gxb + (size_t)tn * GATES + (256 + ubase + v));
            }
        }
        CLUSTER_SYNC();                       // masks0 + mhs visible

        // ---------- build lst0 (ascending, 32 ZROW pads) ----------
        if (tid < 256) {
            int j = tid, pre = 0, tot = 0;
            unsigned mw = 0;
#pragma unroll
            for (int w = 0; w < 8; w++) {
                unsigned mm = msk0[w];
                tot += __popc(mm);
                if (w < (j >> 5)) pre += __popc(mm);
                else if (w == (j >> 5)) {
                    mw = mm;
                    pre += __popc(mm & ((1u << (j & 31)) - 1u));
                }
            }
            if ((mw >> (j & 31)) & 1u) lst0[pre] = j;
            if (j < 32) lst0[tot + j] = ZROW;          // pads (tot+31 <= 287)
            if (j == 0) n0s = (tot + 15) & ~15;
        }
        __syncthreads();

        // ---------------- phase 2 ----------------
        if (tid < 256) {
            // gates1 = ((Wi1.h0 + bi1) + bh1) + Wh1.h1
            float mi = matvec_col(g_WiT1 + ggc, lst0, n0s);
            float gi = __fadd_rn(__fadd_rn(mi, bi1v), bh1v);
            g1s[k256] = __fadd_rn(gi, mhs[k256]);
        } else {
            // precompute m0' = Wh0 . h0(t) for next step's L0 update
            m0s[k256] = matvec_col(g_WhT0 + ggc, lst0, n0s);
        }
        __syncthreads();

        // ---------------- L1 update + output ----------------
        if (tid < 128) {
            float f  = sigmoid_ref(g1s[tid]);
            float ct = g1s[128 + tid];
            float cc = __fadd_rn(__fmul_rn(f, c1s[tid]),
                                 __fmul_rn(__fsub_rn(1.0f, f), ct));
            c1s[tid] = cc;
            float h  = (cc > 0.f) ? 1.f : 0.f;
            out[((size_t)b * SEQ + t) * HID + (ubase + tid)] = h;
            unsigned bal = __ballot_sync(0xffffffffu, cc > 0.f);
            if (lane == 0) {
                msk1[4 * rank + warp] = bal;
                remote_st_u32(&msk1[4 * rank + warp], rank ^ 1, bal);
            }
        }
        CLUSTER_SYNC();                       // masks1 visible

        // ---------- build lst1 (ascending, 32 ZROW pads) ----------
        if (tid < 256) {
            int j = tid, pre = 0, tot = 0;
            unsigned mw = 0;
#pragma unroll
            for (int w = 0; w < 8; w++) {
                unsigned mm = msk1[w];
                tot += __popc(mm);
                if (w < (j >> 5)) pre += __popc(mm);
                else if (w == (j >> 5)) {
                    mw = mm;
                    pre += __popc(mm & ((1u << (j & 31)) - 1u));
                }
            }
            if ((mw >> (j & 31)) & 1u) lst1[pre] = j;
            if (j < 32) lst1[tot + j] = ZROW;
            if (j == 0) n1s = (tot + 15) & ~15;
        }
        __syncthreads();
    }

    // finals: h_n (2,B,H) then c_n (2,B,H) after the (B,S,H) output
    if (tid < 128) {
        const size_t HN = (size_t)BATCH * SEQ * HID;
        const size_t CN = HN + (size_t)2 * BATCH * HID;
        const int ui = ubase + tid;
        float cc0 = c0s[tid], cc1 = c1s[tid];
        out[HN + ((size_t)0 * BATCH + b) * HID + ui] = (cc0 > 0.f) ? 1.f : 0.f;
        out[HN + ((size_t)1 * BATCH + b) * HID + ui] = (cc1 > 0.f) ? 1.f : 0.f;
        out[CN + ((size_t)0 * BATCH + b) * HID + ui] = cc0;
        out[CN + ((size_t)1 * BATCH + b) * HID + ui] = cc1;
    }
}

// ---------------------------------------------------------------
extern "C" void kernel_launch(void* const* d_in, const int* in_sizes, int n_in,
                              void* d_out, int out_size)
{
    const float* x   = (const float*)d_in[0];
    const float* Wi0 = (const float*)d_in[1];
    const float* bi0 = (const float*)d_in[2];
    const float* Wh0 = (const float*)d_in[3];
    const float* bh0 = (const float*)d_in[4];
    const float* Wi1 = (const float*)d_in[5];
    const float* bi1 = (const float*)d_in[6];
    const float* Wh1 = (const float*)d_in[7];
    const float* bh1 = (const float*)d_in[8];
    float* out = (float*)d_out;

    prep_kernel<<<1632, 256>>>(Wh0, Wi1, Wh1);

    dim3 gg(2048, 8);
    gemm_gx_kernel<<<gg, 256>>>(x, Wi0, bi0, bh0);

    recurrent2<<<BATCH * 2, 512>>>(bi1, bh1, out);
}